// round 4
// baseline (speedup 1.0000x reference)
#include <cuda_runtime.h>

#define N_PIX 87040

// contribution of element m (0..15) to output j (0..3): tap T[|m-6-j|] if |m-6-j|<=6
#define CONTRIB2(vv, m)                                             \
    { if ((m) <= 12)              o0 += T[(m) >= 6 ? (m)-6 : 6-(m)] * (vv); \
      if ((m) >= 1 && (m) <= 13)  o1 += T[(m) >= 7 ? (m)-7 : 7-(m)] * (vv); \
      if ((m) >= 2 && (m) <= 14)  o2 += T[(m) >= 8 ? (m)-8 : 8-(m)] * (vv); \
      if ((m) >= 3)               o3 += T[(m) >= 9 ? (m)-9 : 9-(m)] * (vv); }

__global__ __launch_bounds__(512, 4)
void lln_kernel(const float* __restrict__ x, float* __restrict__ out)
{
    // unnormalized 1-D Gaussian taps exp(-k^2/18), sigma=3, radius 6
    const float T[7] = { 1.0f, 0.94595947f, 0.80073740f, 0.60653066f,
                         0.41111229f, 0.24935220f, 0.13533528f };

    const int tile = blockIdx.x;   // 0..21
    const int b    = blockIdx.y;

    int lvl, tloc;
    if      (tile < 16) { lvl = 0; tloc = tile;      }
    else if (tile < 20) { lvl = 1; tloc = tile - 16; }
    else if (tile == 20){ lvl = 2; tloc = 0;         }
    else                { lvl = 3; tloc = 0;         }

    const int dims[4] = {256, 128, 64, 32};
    const int offs[4] = {0, 65536, 81920, 86016};
    const int tprl[4] = {4, 2, 1, 1};

    const int w    = dims[lvl];
    const int h    = w;
    const int ts   = (lvl == 3) ? 32 : 64;   // tile size (square)
    const int tssh = (lvl == 3) ? 5  : 6;
    const int W    = ts + 12;                // halo width

    const int tx0 = (tloc % tprl[lvl]) * 64;
    const int ty0 = (tloc / tprl[lvl]) * 64;

    const int boff = b * (N_PIX * 3) + offs[lvl] * 3;
    const float* __restrict__ base  = x   + boff;
    float*       __restrict__ obase = out + boff;

    // s_mem: luminance [76][76] during phases 1-2, then s_inv [64][65] in phase 3
    __shared__ __align__(16) float s_mem[76 * 76];
    __shared__ __align__(16) float s_h[76][64];
    __shared__ float s_sx[64];
    __shared__ float s_sy[64];

    const int tid = threadIdx.x;

    // ---- dens tables: clipped 1-D tap sums (zero 'SAME' padding) ----
    if (tid < 128) {
        int p = tid & 63;
        int g = ((tid < 64) ? tx0 : ty0) + p;
        float s = T[0];
        s += (g >= 1 ? T[1] : 0.f) + (g >= 2 ? T[2] : 0.f) + (g >= 3 ? T[3] : 0.f)
           + (g >= 4 ? T[4] : 0.f) + (g >= 5 ? T[5] : 0.f) + (g >= 6 ? T[6] : 0.f);
        int d = w - 1 - g;
        s += (d >= 1 ? T[1] : 0.f) + (d >= 2 ? T[2] : 0.f) + (d >= 3 ? T[3] : 0.f)
           + (d >= 4 ? T[4] : 0.f) + (d >= 5 ? T[5] : 0.f) + (d >= 6 ? T[6] : 0.f);
        if (tid < 64) s_sx[p] = s; else s_sy[p] = s;
    }

    // ---- phase 1: luminance gather into s_mem (stride 76), incremental r/c ----
    {
        const int ntask = W * W;
        int t = tid;
        int r = t / W;
        int c = t - r * W;
        const int dr = 512 / W;
        const int dc = 512 - dr * W;
        while (t < ntask) {
            int gy = ty0 - 6 + r;
            int gx = tx0 - 6 + c;
            float v = 0.0f;
            if ((unsigned)gy < (unsigned)h && (unsigned)gx < (unsigned)w) {
                const float* p = base + (gy * w + gx) * 3;
                v = 0.2989f * p[0] + 0.587f * p[1] + 0.114f * p[2];
            }
            s_mem[r * 76 + c] = v;
            t += 512;
            c += dc; r += dr;
            if (c >= W) { c -= W; r += 1; }
        }
    }
    __syncthreads();

    // ---- phase 2: horizontal 13-tap blur, 4 outputs/thread via LDS.128 ----
    {
        const int gc = ts >> 2;          // col-groups per row (16 or 8)
        const int n2 = W * gc;
        for (int t = tid; t < n2; t += 512) {
            int r  = t >> (tssh - 2);
            int cg = (t & (gc - 1)) << 2;
            const float* row = &s_mem[r * 76 + cg];
            float o0 = 0.f, o1 = 0.f, o2 = 0.f, o3 = 0.f;
#pragma unroll
            for (int g = 0; g < 4; g++) {
                float4 q = *(const float4*)(row + 4 * g);
                CONTRIB2(q.x, 4 * g + 0);
                CONTRIB2(q.y, 4 * g + 1);
                CONTRIB2(q.z, 4 * g + 2);
                CONTRIB2(q.w, 4 * g + 3);
            }
            *(float4*)&s_h[r][cg] = make_float4(o0, o1, o2, o3);
        }
    }
    __syncthreads();

    // ---- phase 3a: vertical blur (4 rows/thread) + dens; inv -> s_mem[row*65+c] ----
    {
        const int n3 = ts * (ts >> 2);
        for (int t = tid; t < n3; t += 512) {
            int c  = t & (ts - 1);
            int r0 = (t >> tssh) << 2;
            float o0 = 0.f, o1 = 0.f, o2 = 0.f, o3 = 0.f;
            const float* colp = &s_h[r0][c];
#pragma unroll
            for (int m = 0; m < 16; m++) {
                float vv = colp[m * 64];
                CONTRIB2(vv, m);
            }
            const float sx = s_sx[c];
            {
                float dens = 0.9999f * s_sy[r0 + 0] * sx;
                s_mem[(r0 + 0) * 65 + c] = __fdividef(dens, o0 + 1e-3f * dens);
            }
            {
                float dens = 0.9999f * s_sy[r0 + 1] * sx;
                s_mem[(r0 + 1) * 65 + c] = __fdividef(dens, o1 + 1e-3f * dens);
            }
            {
                float dens = 0.9999f * s_sy[r0 + 2] * sx;
                s_mem[(r0 + 2) * 65 + c] = __fdividef(dens, o2 + 1e-3f * dens);
            }
            {
                float dens = 0.9999f * s_sy[r0 + 3] * sx;
                s_mem[(r0 + 3) * 65 + c] = __fdividef(dens, o3 + 1e-3f * dens);
            }
        }
    }
    __syncthreads();

    // ---- phase 3b: vectorized I/O. Tile row = ts*3 floats = 48 (or 24) float4 ----
    {
        const int fpr = 3 << (tssh - 2);     // float4 per tile row (48 or 24)
        const int n4  = ts * fpr;
        for (int t = tid; t < n4; t += 512) {
            int q3  = (t * 21846) >> 16;          // t/3 (exact for t < 3072)
            int row = q3 >> (tssh - 2);           // t / fpr
            int f   = t - row * fpr;
            int u   = f << 2;                     // first float in row (0..188)
            int p0  = (u * 21846) >> 16;          // u/3
            int fm3 = u - 3 * p0;
            int th  = 3 - fm3;

            const float* invrow = &s_mem[row * 65];
            float iA = invrow[p0];
            float iB = invrow[p0 + 1];

            int goff = ((ty0 + row) * w + tx0) * 3 + u;
            float4 q = *(const float4*)(base + goff);
            q.x *= iA;
            q.y *= (1 < th) ? iA : iB;
            q.z *= (2 < th) ? iA : iB;
            q.w *= iB;
            *(float4*)(obase + goff) = q;
        }
    }
}

extern "C" void kernel_launch(void* const* d_in, const int* in_sizes, int n_in,
                              void* d_out, int out_size)
{
    const float* x = (const float*)d_in[0];
    float* out     = (float*)d_out;
    dim3 grid(22, 128);
    lln_kernel<<<grid, 512>>>(x, out);
}

// round 6
// speedup vs baseline: 1.1861x; 1.1861x over previous
#include <cuda_runtime.h>

#define TS   32
#define HALO 6
#define LW   44
#define N_PIX 87040

struct SMem {
    float lum[LW * LW];        // 44x44 luminance incl. halo
    float hT [TS * LW];        // H-blurred, TRANSPOSED: [col*44 + row]
    float inv[TS * (TS + 1)];  // per-pixel 1/denominator (stride 33)
    float sx [TS];
    float sy [TS];
};

// contribution of element m (0..15) to output j (0..3): tap T[|m-6-j|] if <=6
#define CONTRIB2(vv, m)                                             \
    { if ((m) <= 12)              o0 += T[(m) >= 6 ? (m)-6 : 6-(m)] * (vv); \
      if ((m) >= 1 && (m) <= 13)  o1 += T[(m) >= 7 ? (m)-7 : 7-(m)] * (vv); \
      if ((m) >= 2 && (m) <= 14)  o2 += T[(m) >= 8 ? (m)-8 : 8-(m)] * (vv); \
      if ((m) >= 3)               o3 += T[(m) >= 9 ? (m)-9 : 9-(m)] * (vv); }

template<int W>
__device__ __forceinline__ void run_tile(int tloc, const float* __restrict__ base,
                                         float* __restrict__ obase, SMem& sm, int tid)
{
    const float T[7] = { 1.0f, 0.94595947f, 0.80073740f, 0.60653066f,
                         0.41111229f, 0.24935220f, 0.13533528f };
    constexpr int TPR = W / TS;

    const int tx0 = (tloc & (TPR - 1)) * TS;
    const int ty0 = (tloc / TPR) * TS;

    // ---- dens tables: clipped 1-D tap sums (zero 'SAME' padding) ----
    if (tid < 64) {
        int p = tid & 31;
        int g = (tid < 32 ? tx0 : ty0) + p;
        float s = T[0];
        s += (g >= 1 ? T[1] : 0.f) + (g >= 2 ? T[2] : 0.f) + (g >= 3 ? T[3] : 0.f)
           + (g >= 4 ? T[4] : 0.f) + (g >= 5 ? T[5] : 0.f) + (g >= 6 ? T[6] : 0.f);
        int d = W - 1 - g;
        s += (d >= 1 ? T[1] : 0.f) + (d >= 2 ? T[2] : 0.f) + (d >= 3 ? T[3] : 0.f)
           + (d >= 4 ? T[4] : 0.f) + (d >= 5 ? T[5] : 0.f) + (d >= 6 ? T[6] : 0.f);
        if (tid < 32) sm.sx[p] = s; else sm.sy[p] = s;
    }

    // ---- phase 1: luminance gather ----
    {
        int r = tid / 44;
        int c = tid - r * 44;
        const bool interior = (W >= 128) && (tx0 >= HALO) && (ty0 >= HALO) &&
                              (tx0 + TS + HALO <= W) && (ty0 + TS + HALO <= W);
        if (interior) {
            int goff = ((ty0 - HALO + r) * W + (tx0 - HALO + c)) * 3;
            constexpr int dA = (5 * W + 36) * 3;
            constexpr int dB = (6 * W - 8) * 3;
            int idx = tid;
#pragma unroll
            for (int it = 0; it < 7; it++) {
                const float* p = base + goff;
                sm.lum[idx] = 0.2989f * p[0] + 0.587f * p[1] + 0.114f * p[2];
                idx += 256;
                int cn = c + 36;
                bool wrap = cn >= 44;
                c = wrap ? cn - 44 : cn;
                goff += wrap ? dB : dA;
            }
            if (idx < LW * LW) {
                const float* p = base + goff;
                sm.lum[idx] = 0.2989f * p[0] + 0.587f * p[1] + 0.114f * p[2];
            }
        } else {
            int gy = ty0 - HALO + r;
            int gx = tx0 - HALO + c;
            int idx = tid;
#pragma unroll
            for (int it = 0; it < 8; it++) {
                if (idx < LW * LW) {
                    float v = 0.0f;
                    if ((unsigned)gy < (unsigned)W && (unsigned)gx < (unsigned)W) {
                        const float* p = base + (gy * W + gx) * 3;
                        v = 0.2989f * p[0] + 0.587f * p[1] + 0.114f * p[2];
                    }
                    sm.lum[idx] = v;
                }
                idx += 256;
                int gxn = gx + 36;
                bool wrap = gxn >= tx0 - HALO + 44;
                gx = wrap ? gxn - 44 : gxn;
                gy += wrap ? 6 : 5;
            }
        }
    }
    __syncthreads();

    // ---- phase 2: horizontal blur; task t = cg*44 + r; store transposed ----
    {
        int cg = tid / 44;           // col-group 0..7
        int r  = tid - cg * 44;      // row 0..43
        int t  = tid;
#pragma unroll
        for (int pass = 0; pass < 2; pass++) {
            if (t < 352) {
                const float* row = &sm.lum[r * 44 + 4 * cg];
                float o0 = 0.f, o1 = 0.f, o2 = 0.f, o3 = 0.f;
#pragma unroll
                for (int g = 0; g < 4; g++) {
                    float4 q = *(const float4*)(row + 4 * g);
                    CONTRIB2(q.x, 4 * g + 0);
                    CONTRIB2(q.y, 4 * g + 1);
                    CONTRIB2(q.z, 4 * g + 2);
                    CONTRIB2(q.w, 4 * g + 3);
                }
                float* dst = &sm.hT[(4 * cg) * 44 + r];
                dst[0]   = o0;
                dst[44]  = o1;
                dst[88]  = o2;
                dst[132] = o3;
            }
            t += 256;
            cg += 5;
            r  += 36;
            if (r >= 44) { r -= 44; cg += 1; }
        }
    }
    __syncthreads();

    // ---- phase 3a: vertical blur (4 rows/thread) via LDS.128 + dens ----
    {
        const int c  = tid & 31;
        const int r0 = (tid >> 5) << 2;
        const float* colp = &sm.hT[c * 44 + r0];   // 16B-aligned
        float a[16];
#pragma unroll
        for (int m = 0; m < 16; m++) a[m] = colp[m];

        float o0 = 0.f, o1 = 0.f, o2 = 0.f, o3 = 0.f;
#pragma unroll
        for (int m = 0; m < 16; m++) { CONTRIB2(a[m], m); }

        const float sx = sm.sx[c];
        float* invp = &sm.inv[r0 * 33 + c];
        {
            float dens = 0.9999f * sm.sy[r0 + 0] * sx;
            invp[0]      = __fdividef(dens, o0 + 1e-3f * dens);
        }
        {
            float dens = 0.9999f * sm.sy[r0 + 1] * sx;
            invp[33]     = __fdividef(dens, o1 + 1e-3f * dens);
        }
        {
            float dens = 0.9999f * sm.sy[r0 + 2] * sx;
            invp[66]     = __fdividef(dens, o2 + 1e-3f * dens);
        }
        {
            float dens = 0.9999f * sm.sy[r0 + 3] * sx;
            invp[99]     = __fdividef(dens, o3 + 1e-3f * dens);
        }
    }
    __syncthreads();

    // ---- phase 3b: vectorized I/O; 32 rows x 24 float4 = 768 = 3*256 tasks ----
    {
        int row = (tid * 21846) >> 19;   // tid/24 (exact for tid<768)
        int f   = tid - row * 24;
#pragma unroll
        for (int it = 0; it < 3; it++) {
            int u   = f << 2;                 // first float in row (0..92)
            int p0  = (u * 21846) >> 16;      // u/3
            int fm3 = u - 3 * p0;
            int th  = 3 - fm3;

            const float* invrow = &sm.inv[row * 33];
            float iA = invrow[p0];
            float iB = invrow[p0 + 1];

            int goff = ((ty0 + row) * W + tx0) * 3 + u;
            float4 q = *(const float4*)(base + goff);
            q.x *= iA;
            q.y *= (1 < th) ? iA : iB;
            q.z *= (2 < th) ? iA : iB;
            q.w *= iB;
            *(float4*)(obase + goff) = q;

            row += 10;
            f   += 16;
            if (f >= 24) { f -= 24; row += 1; }
        }
    }
}

__global__ __launch_bounds__(256, 8)
void lln_kernel(const float* __restrict__ x, float* __restrict__ out)
{
    __shared__ SMem sm;
    const int tile = blockIdx.x;
    const int b    = blockIdx.y;
    const int tid  = threadIdx.x;
    const int bo   = b * (N_PIX * 3);

    if (tile < 64) {
        run_tile<256>(tile,      x + bo,              out + bo,              sm, tid);
    } else if (tile < 80) {
        run_tile<128>(tile - 64, x + bo + 65536 * 3,  out + bo + 65536 * 3,  sm, tid);
    } else if (tile < 84) {
        run_tile<64> (tile - 80, x + bo + 81920 * 3,  out + bo + 81920 * 3,  sm, tid);
    } else {
        run_tile<32> (0,         x + bo + 86016 * 3,  out + bo + 86016 * 3,  sm, tid);
    }
}

extern "C" void kernel_launch(void* const* d_in, const int* in_sizes, int n_in,
                              void* d_out, int out_size)
{
    const float* x = (const float*)d_in[0];
    float* out     = (float*)d_out;
    dim3 grid(85, 128);
    lln_kernel<<<grid, 256>>>(x, out);
}